// round 10
// baseline (speedup 1.0000x reference)
#include <cuda_runtime.h>
#include <math.h>

#define BATCH 512
#define NGEN 4095
#define THETA_STRIDE 4096
#define HID 256
#define INDIM 768
#define CHUNK 512
#define NOBS 15

typedef unsigned long long ull;

// ---------------- f32x2 packed helpers (Blackwell) ----------------
__device__ __forceinline__ ull pk2(float lo, float hi) {
    ull r; asm("mov.b64 %0, {%1, %2};" : "=l"(r) : "f"(lo), "f"(hi)); return r;
}
__device__ __forceinline__ void upk2(ull v, float& lo, float& hi) {
    asm("mov.b64 {%0, %1}, %2;" : "=f"(lo), "=f"(hi) : "l"(v));
}
__device__ __forceinline__ ull fma2(ull a, ull b, ull c) {
    ull d; asm("fma.rn.f32x2 %0, %1, %2, %3;" : "=l"(d) : "l"(a), "l"(b), "l"(c)); return d;
}

// ---------------- scratch ----------------
__device__ float g_hid[BATCH * HID];
__device__ float g_theta[BATCH * THETA_STRIDE];
__device__ float g_hid2[BATCH * HID];

// ---------------- small-grid GEMM (64x64 tile) for g1/g4 ----------------
template <bool SILU>
__global__ void gemm_kernel(const float* __restrict__ A, const float* __restrict__ B,
                            const float* __restrict__ bias, float* __restrict__ C,
                            int M, int N, int K, int lda, int ldc)
{
    const int BM = 64, BN = 64, BK = 16;
    __shared__ __align__(16) float As2[BK][BM * 2];
    __shared__ __align__(16) float Bs[BK][BN];
    int tid = threadIdx.x;
    int tx = tid % 16, ty = tid / 16;
    int brow = blockIdx.y * BM, bcol = blockIdx.x * BN;

    ull acc[4][2];
#pragma unroll
    for (int i = 0; i < 4; ++i) { acc[i][0] = 0ull; acc[i][1] = 0ull; }

    for (int k0 = 0; k0 < K; k0 += BK) {
#pragma unroll
        for (int i = tid; i < BM * BK; i += 256) {
            int r = i / BK, c = i % BK;
            int gr = brow + r, gc = k0 + c;
            float v = (gr < M && gc < K) ? A[gr * lda + gc] : 0.f;
            *reinterpret_cast<float2*>(&As2[c][2 * r]) = make_float2(v, v);
        }
#pragma unroll
        for (int i = tid; i < BK * BN; i += 256) {
            int r = i / BN, c = i % BN;
            int gr = k0 + r, gc = bcol + c;
            Bs[r][c] = (gr < K && gc < N) ? B[gr * N + gc] : 0.f;
        }
        __syncthreads();
#pragma unroll
        for (int kk = 0; kk < BK; ++kk) {
            ulonglong2 aA = *reinterpret_cast<const ulonglong2*>(&As2[kk][ty * 8]);
            ulonglong2 aB = *reinterpret_cast<const ulonglong2*>(&As2[kk][ty * 8 + 4]);
            ulonglong2 bb = *reinterpret_cast<const ulonglong2*>(&Bs[kk][tx * 4]);
            acc[0][0] = fma2(aA.x, bb.x, acc[0][0]); acc[0][1] = fma2(aA.x, bb.y, acc[0][1]);
            acc[1][0] = fma2(aA.y, bb.x, acc[1][0]); acc[1][1] = fma2(aA.y, bb.y, acc[1][1]);
            acc[2][0] = fma2(aB.x, bb.x, acc[2][0]); acc[2][1] = fma2(aB.x, bb.y, acc[2][1]);
            acc[3][0] = fma2(aB.y, bb.x, acc[3][0]); acc[3][1] = fma2(aB.y, bb.y, acc[3][1]);
        }
        __syncthreads();
    }
#pragma unroll
    for (int i = 0; i < 4; ++i) {
        int row = brow + ty * 4 + i;
        if (row >= M) continue;
#pragma unroll
        for (int p = 0; p < 2; ++p) {
            float c0, c1;
            upk2(acc[i][p], c0, c1);
            int col0 = bcol + tx * 4 + 2 * p;
            if (col0 < N) {
                float v = c0 + bias[col0];
                if (SILU) v = v / (1.f + expf(-v));
                C[row * ldc + col0] = v;
            }
            if (col0 + 1 < N) {
                float v = c1 + bias[col0 + 1];
                if (SILU) v = v / (1.f + expf(-v));
                C[row * ldc + col0 + 1] = v;
            }
        }
    }
}

// ---------------- big GEMM v3: 64x128 tile, TM=4 x TN=8, BK=16, double-buffered ----------------
// 256 threads = 16tx (8 N-cols each) x 16ty (4 M-rows each). acc = 16 ull (32 regs).
// Grid 256 CTAs -> 2 CTAs/SM, 16 warps/SM, single wave.
#define AS3_S 132
__global__ __launch_bounds__(256, 2) void gemm128_kernel(
    const float* __restrict__ A, const float* __restrict__ B,
    const float* __restrict__ bias, float* __restrict__ C,
    int M, int N, int K, int lda, int ldc)
{
    __shared__ __align__(16) float As2[2][16][AS3_S];   // 64 rows duplicated (a,a)
    __shared__ __align__(16) float Bs[2][16][128];
    const int tid = threadIdx.x;
    const int tx = tid & 15, ty = tid >> 4;
    const int brow = blockIdx.y * 64, bcol = blockIdx.x * 128;

    const int ar = tid >> 2, ac4 = (tid & 3) * 4;      // A: float4 at (row ar, cols ac4..+3)
    const int br = tid >> 5, bc4 = (tid & 31) * 4;     // B: rows br, br+8; cols bc4..+3

    ull acc[4][4];
#pragma unroll
    for (int i = 0; i < 4; ++i)
#pragma unroll
        for (int j = 0; j < 4; ++j) acc[i][j] = 0ull;

    const int nk = K >> 4;   // K multiple of 16

    float4 a_st;
    float b_st[8];

    // preload block 0
    {
        a_st = *reinterpret_cast<const float4*>(&A[(brow + ar) * lda + ac4]);
        int gcb = bcol + bc4;
#pragma unroll
        for (int j = 0; j < 4; ++j) {
            b_st[j]     = (gcb + j < N) ? B[br * N + gcb + j] : 0.f;
            b_st[4 + j] = (gcb + j < N) ? B[(br + 8) * N + gcb + j] : 0.f;
        }
        float* a0 = &As2[0][ac4][2 * ar];
        a0[0] = a_st.x; a0[1] = a_st.x;
        float* a1 = &As2[0][ac4 + 1][2 * ar];
        a1[0] = a_st.y; a1[1] = a_st.y;
        float* a2 = &As2[0][ac4 + 2][2 * ar];
        a2[0] = a_st.z; a2[1] = a_st.z;
        float* a3 = &As2[0][ac4 + 3][2 * ar];
        a3[0] = a_st.w; a3[1] = a_st.w;
#pragma unroll
        for (int j = 0; j < 4; ++j) {
            Bs[0][br][bc4 + j]     = b_st[j];
            Bs[0][br + 8][bc4 + j] = b_st[4 + j];
        }
    }
    __syncthreads();

    for (int kb = 0; kb < nk; ++kb) {
        int cur = kb & 1;
        if (kb + 1 < nk) {
            int k0 = (kb + 1) * 16;
            a_st = *reinterpret_cast<const float4*>(&A[(brow + ar) * lda + k0 + ac4]);
            int gcb = bcol + bc4;
#pragma unroll
            for (int j = 0; j < 4; ++j) {
                b_st[j]     = (gcb + j < N) ? B[(k0 + br) * N + gcb + j] : 0.f;
                b_st[4 + j] = (gcb + j < N) ? B[(k0 + br + 8) * N + gcb + j] : 0.f;
            }
        }
#pragma unroll
        for (int kk = 0; kk < 16; ++kk) {
            ulonglong2 a01 = *reinterpret_cast<const ulonglong2*>(&As2[cur][kk][ty * 8]);
            ulonglong2 a23 = *reinterpret_cast<const ulonglong2*>(&As2[cur][kk][ty * 8 + 4]);
            ulonglong2 b03 = *reinterpret_cast<const ulonglong2*>(&Bs[cur][kk][tx * 8]);
            ulonglong2 b47 = *reinterpret_cast<const ulonglong2*>(&Bs[cur][kk][tx * 8 + 4]);
            ull arr[4] = {a01.x, a01.y, a23.x, a23.y};
            ull brr[4] = {b03.x, b03.y, b47.x, b47.y};
#pragma unroll
            for (int r = 0; r < 4; ++r)
#pragma unroll
                for (int p = 0; p < 4; ++p)
                    acc[r][p] = fma2(arr[r], brr[p], acc[r][p]);
        }
        if (kb + 1 < nk) {
            int nxt = (kb + 1) & 1;
            float* a0 = &As2[nxt][ac4][2 * ar];
            a0[0] = a_st.x; a0[1] = a_st.x;
            float* a1 = &As2[nxt][ac4 + 1][2 * ar];
            a1[0] = a_st.y; a1[1] = a_st.y;
            float* a2 = &As2[nxt][ac4 + 2][2 * ar];
            a2[0] = a_st.z; a2[1] = a_st.z;
            float* a3 = &As2[nxt][ac4 + 3][2 * ar];
            a3[0] = a_st.w; a3[1] = a_st.w;
#pragma unroll
            for (int j = 0; j < 4; ++j) {
                Bs[nxt][br][bc4 + j]     = b_st[j];
                Bs[nxt][br + 8][bc4 + j] = b_st[4 + j];
            }
        }
        __syncthreads();
    }

#pragma unroll
    for (int rr = 0; rr < 4; ++rr) {
        int row = brow + ty * 4 + rr;
#pragma unroll
        for (int p = 0; p < 4; ++p) {
            float c0, c1;
            upk2(acc[rr][p], c0, c1);
            int col0 = bcol + tx * 8 + 2 * p;
            if (col0 < N)     C[row * ldc + col0]     = c0 + bias[col0];
            if (col0 + 1 < N) C[row * ldc + col0 + 1] = c1 + bias[col0 + 1];
        }
    }
}

__global__ void dummy_kernel() {}

// ---------------- quantum kernel v5: RMT lambda, broadcast matvec ----------------
__device__ __forceinline__ int spread6(int v) {
    return (v & 1) | ((v & 2) << 1) | ((v & 4) << 2) | ((v & 8) << 3) |
           ((v & 16) << 4) | ((v & 32) << 5);
}

__device__ __forceinline__ void pauli_coef_raw(int x, int z, const float* __restrict__ th,
                                               float& cr, float& ci)
{
    if ((x | z) == 0) { cr = 0.f; ci = 0.f; return; }
    int idx4 = spread6(x ^ z) | (spread6(z) << 1);
    float v = __ldg(th + idx4 - 1);
    int p = __popc(x & z) & 3;               // (-i)^p
    cr = (p == 0) ? v : ((p == 2) ? -v : 0.f);
    ci = (p == 1) ? -v : ((p == 3) ? v : 0.f);
}

#define PHASEA() do {                                                              \
    const float4* _vp = reinterpret_cast<const float4*>(&vv[buf][slice * 8]);      \
    float4 _a0 = _vp[0], _a1 = _vp[1];                                             \
    float _pr0, _pi0, _pr1, _pi1;                                                  \
    _pr0 = hr[0] * _a0.x - hi[0] * _a0.y;  _pi0 = hr[0] * _a0.y + hi[0] * _a0.x;   \
    _pr1 = hr[1] * _a0.z - hi[1] * _a0.w;  _pi1 = hr[1] * _a0.w + hi[1] * _a0.z;   \
    _pr0 += hr[2] * _a1.x - hi[2] * _a1.y; _pi0 += hr[2] * _a1.y + hi[2] * _a1.x;  \
    _pr1 += hr[3] * _a1.z - hi[3] * _a1.w; _pi1 += hr[3] * _a1.w + hi[3] * _a1.z;  \
    float4 _a2 = _vp[2], _a3 = _vp[3];                                             \
    _pr0 += hr[4] * _a2.x - hi[4] * _a2.y; _pi0 += hr[4] * _a2.y + hi[4] * _a2.x;  \
    _pr1 += hr[5] * _a2.z - hi[5] * _a2.w; _pi1 += hr[5] * _a2.w + hi[5] * _a2.z;  \
    _pr0 += hr[6] * _a3.x - hi[6] * _a3.y; _pi0 += hr[6] * _a3.y + hi[6] * _a3.x;  \
    _pr1 += hr[7] * _a3.z - hi[7] * _a3.w; _pi1 += hr[7] * _a3.w + hi[7] * _a3.z;  \
    spart[slice * 64 + row] = make_float2(_pr0 + _pr1, _pi0 + _pi1);               \
} while (0)

__global__ __launch_bounds__(512, 3) void quantum_kernel(
    const float* __restrict__ theta_all,
    const float* __restrict__ Aoff, const float* __restrict__ Boff,
    const float* __restrict__ Ddiag,
    const float* __restrict__ Wv1, const float* __restrict__ bv1,
    float* __restrict__ hid2_out)
{
    const int b = blockIdx.x;
    const float* th = theta_all + b * THETA_STRIDE;
    const int t = threadIdx.x;
    const int lane = t & 31, warp = t >> 5;

    __shared__ float sHr[64 * 65];
    __shared__ float sHi[64 * 65];
    __shared__ __align__(16) float2 vv[2][64];
    __shared__ __align__(16) float2 spart[512];
    __shared__ float spr[64], spi[64];
    __shared__ float sJ[128];
    __shared__ float s_sin[128];
    __shared__ float sred[16];
    __shared__ float s_scl[4];
    __shared__ float sq[16];
    __shared__ int s_K;

    // --- sum theta^2 -> lambda_F ---
    float ss = 0.f;
    for (int m = t; m < NGEN; m += 512) { float v = __ldg(th + m); ss += v * v; }
#pragma unroll
    for (int d = 16; d; d >>= 1) ss += __shfl_xor_sync(0xffffffffu, ss, d);
    if (lane == 0) sred[warp] = ss;

    // --- quadrature sin table (128-pt) ---
    if (t < 128) s_sin[t] = __sinf((float)t * 0.049087385212f);  // 2*pi/128

    // --- build raw H via 64-pt WHT per x-mask (16 warps -> 4 passes) ---
    for (int pass = 0; pass < 4; ++pass) {
        int x = pass * 16 + warp;
        float ar, ai, br, bi;
        pauli_coef_raw(x, lane, th, ar, ai);
        pauli_coef_raw(x, lane + 32, th, br, bi);
        float t0r = ar + br, t0i = ai + bi;
        float t1r = ar - br, t1i = ai - bi;
#pragma unroll
        for (int d = 16; d >= 1; d >>= 1) {
            float o;
            o = __shfl_xor_sync(0xffffffffu, t0r, d); t0r = (lane & d) ? (o - t0r) : (t0r + o);
            o = __shfl_xor_sync(0xffffffffu, t0i, d); t0i = (lane & d) ? (o - t0i) : (t0i + o);
            o = __shfl_xor_sync(0xffffffffu, t1r, d); t1r = (lane & d) ? (o - t1r) : (t1r + o);
            o = __shfl_xor_sync(0xffffffffu, t1i, d); t1i = (lane & d) ? (o - t1i) : (t1i + o);
        }
        sHr[lane * 65 + (lane ^ x)] = t0r;
        sHi[lane * 65 + (lane ^ x)] = t0i;
        int r2 = lane + 32;
        sHr[r2 * 65 + (r2 ^ x)] = t1r;
        sHi[r2 * 65 + (r2 ^ x)] = t1i;
    }
    __syncthreads();

    // --- stage H slice: row = t&63, slice = t>>6 ---
    const int row = t & 63, slice = t >> 6, cb = slice * 8;
    float hr[8], hi[8];
#pragma unroll
    for (int j = 0; j < 8; ++j) {
        hr[j] = sHr[row * 65 + cb + j];
        hi[j] = sHi[row * 65 + cb + j];
    }

    // --- RMT lambda + K (thread 0), e0 init ---
    if (t == 0) {
        float tot = 0.f;
#pragma unroll
        for (int i = 0; i < 16; ++i) tot += sred[i];
        float lamF = sqrtf(64.f * fmaxf(tot, 1e-12f));
        float lu = fmaxf(0.285f * lamF, 1e-3f);
        int K = (int)ceilf(lu + 3.0f * cbrtf(lu) + 2.f);
        if (K < 6) K = 6;
        if (K > 99) K = 99;
        s_scl[0] = lu;
        s_scl[1] = 1.f / lu;
        s_K = K;
    }
    if (t < 64) vv[0][t] = make_float2((t == 0) ? 1.f : 0.f, 0.f);
    __syncthreads();
    const float invl = s_scl[1];
    const int K = s_K;

    // --- Bessel J_k via 128-pt DFT quadrature ---
    if (t < 128) s_sin[t] *= s_scl[0];
    __syncthreads();
    {
        int k = t >> 2, jb = t & 3;
        const float C0 = 0.049087385212f;  // 2*pi/128
        int idx = (k * jb) & 127;
        int step = (4 * k) & 127;
        float sum = 0.f;
        int j = jb;
#pragma unroll 8
        for (int i = 0; i < 32; ++i) {
            float ang = fmaf((float)idx, C0, -s_sin[j]);
            sum += __cosf(ang);
            idx = (idx + step) & 127;
            j += 4;
        }
        sum += __shfl_xor_sync(0xffffffffu, sum, 1);
        sum += __shfl_xor_sync(0xffffffffu, sum, 2);
        if (jb == 0) sJ[k] = sum * (1.f / 128.f);
    }
    __syncthreads();

    // --- Chebyshev: psi = sum c_k T_k(H/lu) e0 ---
    int buf = 0;
    float cur_r = 0.f, cur_i = 0.f, prev_r = 0.f, prev_i = 0.f;
    float psi_r = 0.f, psi_i = 0.f;
    if (t < 64) {
        cur_r = (t == 0) ? 1.f : 0.f;
        psi_r = sJ[0] * cur_r;
    }

    for (int k = 1; k <= K; ++k) {
        PHASEA();
        __syncthreads();
        if (t < 64) {
            float ar = 0.f, ai = 0.f;
#pragma unroll
            for (int s = 0; s < 8; ++s) {
                float2 p = spart[s * 64 + t];
                ar += p.x; ai += p.y;
            }
            ar *= invl; ai *= invl;
            float tnr, tni;
            if (k == 1) { tnr = ar; tni = ai; }
            else        { tnr = 2.f * ar - prev_r; tni = 2.f * ai - prev_i; }
            float cj = 2.f * sJ[k];
            switch (k & 3) {
                case 0: psi_r += cj * tnr; psi_i += cj * tni; break;
                case 1: psi_r -= cj * tni; psi_i += cj * tnr; break;
                case 2: psi_r -= cj * tnr; psi_i -= cj * tni; break;
                case 3: psi_r += cj * tni; psi_i -= cj * tnr; break;
            }
            prev_r = cur_r; prev_i = cur_i;
            cur_r = tnr;    cur_i = tni;
            vv[buf ^ 1][t] = make_float2(tnr, tni);
        }
        __syncthreads();
        buf ^= 1;
    }
    if (t < 64) { spr[t] = psi_r; spi[t] = psi_i; }

    // --- renormalize |psi> ---
    {
        float n = (t < 64) ? (psi_r * psi_r + psi_i * psi_i) : 0.f;
#pragma unroll
        for (int d = 16; d; d >>= 1) n += __shfl_xor_sync(0xffffffffu, n, d);
        if (lane == 0) sred[warp] = n;
        __syncthreads();
        if (t == 0) {
            float tot = sred[0] + sred[1];
            s_scl[2] = 1.f / fmaxf(tot, 1e-30f);
        }
        __syncthreads();
    }

    // --- 15 two-local observables -> sq ---
    if (t < NOBS) {
        const int wa[15] = {0,0,0,0,0,1,1,1,1,2,2,2,3,3,4};
        const int wb[15] = {1,2,3,4,5,2,3,4,5,3,4,5,4,5,5};
        int a = wa[t], bq = wb[t];
        int pa = 5 - a, pb = 5 - bq;
        float Hd[4];
        Hd[0] = 2.f * __ldg(Ddiag + t * 4 + 1);
        Hd[1] = 2.f * __ldg(Ddiag + t * 4 + 2);
        Hd[2] = 2.f * __ldg(Ddiag + t * 4 + 3);
        Hd[3] = 0.f;
        float Ac[6], Bc[6];
#pragma unroll
        for (int c = 0; c < 6; ++c) {
            Ac[c] = __ldg(Aoff + t * 6 + c);
            Bc[c] = __ldg(Boff + t * 6 + c);
        }
        const int kk_[6] = {1, 2, 2, 3, 3, 3};
        const int ll_[6] = {0, 0, 1, 0, 1, 2};
        float q = 0.f;
        for (int r = 0; r < 16; ++r) {
            int idx0 = 0, rr = r;
#pragma unroll
            for (int p = 0; p < 6; ++p) {
                if (p != pa && p != pb) { idx0 |= (rr & 1) << p; rr >>= 1; }
            }
            float xr[4], xi[4];
#pragma unroll
            for (int k = 0; k < 4; ++k) {
                int idx = idx0 | (((k >> 1) & 1) << pa) | ((k & 1) << pb);
                xr[k] = spr[idx]; xi[k] = spi[idx];
            }
#pragma unroll
            for (int k = 0; k < 4; ++k) q += Hd[k] * (xr[k] * xr[k] + xi[k] * xi[k]);
#pragma unroll
            for (int c = 0; c < 6; ++c) {
                int k = kk_[c], l = ll_[c];
                float rr2 = xr[k] * xr[l] + xi[k] * xi[l];
                float ii2 = xi[k] * xr[l] - xr[k] * xi[l];
                q += 2.f * (Ac[c] * rr2 + Bc[c] * ii2);
            }
        }
        sq[t] = q * s_scl[2];
    }
    __syncthreads();

    // --- fused vel-head layer 1 (first 256 threads) ---
    if (t < HID) {
        float h = __ldg(bv1 + t);
#pragma unroll
        for (int o = 0; o < NOBS; ++o) h = fmaf(sq[o], __ldg(Wv1 + o * HID + t), h);
        h = h / (1.f + expf(-h));
        hid2_out[b * HID + t] = h;
    }
}

// ---------------- launch ----------------
extern "C" void kernel_launch(void* const* d_in, const int* in_sizes, int n_in,
                              void* d_out, int out_size)
{
    const float* x    = (const float*)d_in[0];
    const float* W1   = (const float*)d_in[1];
    const float* b1   = (const float*)d_in[2];
    const float* W2   = (const float*)d_in[3];
    const float* b2   = (const float*)d_in[4];
    const float* Aoff = (const float*)d_in[5];
    const float* Boff = (const float*)d_in[6];
    const float* Dd   = (const float*)d_in[7];
    const float* Wv1  = (const float*)d_in[8];
    const float* bv1  = (const float*)d_in[9];
    const float* Wv2  = (const float*)d_in[10];
    const float* bv2  = (const float*)d_in[11];
    float* out = (float*)d_out;

    float* hid;   cudaGetSymbolAddress((void**)&hid,   g_hid);
    float* theta; cudaGetSymbolAddress((void**)&theta, g_theta);
    float* hid2;  cudaGetSymbolAddress((void**)&hid2,  g_hid2);

    {
        dim3 g((HID + 63) / 64, (BATCH + 63) / 64);
        gemm_kernel<true><<<g, 256>>>(x, W1, b1, hid, BATCH, HID, INDIM, INDIM, HID);
    }
    // two dummies so the NEW gemm128 is my 4th launch (ncu -s 5 -c 1 captures it)
    dummy_kernel<<<1, 1>>>();
    dummy_kernel<<<1, 1>>>();
    {
        dim3 g((NGEN + 127) / 128, (BATCH + 63) / 64);
        gemm128_kernel<<<g, 256>>>(hid, W2, b2, theta, BATCH, NGEN, HID, HID, THETA_STRIDE);
    }
    quantum_kernel<<<BATCH, 512>>>(theta, Aoff, Boff, Dd, Wv1, bv1, hid2);
    {
        dim3 g((CHUNK + 63) / 64, (BATCH + 63) / 64);
        gemm_kernel<false><<<g, 256>>>(hid2, Wv2, bv2, out, BATCH, CHUNK, HID, HID, CHUNK);
    }
}

// round 11
// speedup vs baseline: 1.0911x; 1.0911x over previous
#include <cuda_runtime.h>
#include <math.h>

#define BATCH 512
#define NGEN 4095
#define THETA_STRIDE 4096
#define HID 256
#define INDIM 768
#define CHUNK 512
#define NOBS 15

typedef unsigned long long ull;

// ---------------- f32x2 packed helpers (Blackwell) ----------------
__device__ __forceinline__ ull pk2(float lo, float hi) {
    ull r; asm("mov.b64 %0, {%1, %2};" : "=l"(r) : "f"(lo), "f"(hi)); return r;
}
__device__ __forceinline__ void upk2(ull v, float& lo, float& hi) {
    asm("mov.b64 {%0, %1}, %2;" : "=f"(lo), "=f"(hi) : "l"(v));
}
__device__ __forceinline__ ull fma2(ull a, ull b, ull c) {
    ull d; asm("fma.rn.f32x2 %0, %1, %2, %3;" : "=l"(d) : "l"(a), "l"(b), "l"(c)); return d;
}

// ---------------- scratch ----------------
__device__ float g_hid[BATCH * HID];
__device__ float g_theta[BATCH * THETA_STRIDE];
__device__ float g_hid2[BATCH * HID];

// ---------------- small-grid GEMM (64x64 tile) for g1/g4 ----------------
template <bool SILU>
__global__ void gemm_kernel(const float* __restrict__ A, const float* __restrict__ B,
                            const float* __restrict__ bias, float* __restrict__ C,
                            int M, int N, int K, int lda, int ldc)
{
    const int BM = 64, BN = 64, BK = 16;
    __shared__ __align__(16) float As2[BK][BM * 2];
    __shared__ __align__(16) float Bs[BK][BN];
    int tid = threadIdx.x;
    int tx = tid % 16, ty = tid / 16;
    int brow = blockIdx.y * BM, bcol = blockIdx.x * BN;

    ull acc[4][2];
#pragma unroll
    for (int i = 0; i < 4; ++i) { acc[i][0] = 0ull; acc[i][1] = 0ull; }

    for (int k0 = 0; k0 < K; k0 += BK) {
#pragma unroll
        for (int i = tid; i < BM * BK; i += 256) {
            int r = i / BK, c = i % BK;
            int gr = brow + r, gc = k0 + c;
            float v = (gr < M && gc < K) ? A[gr * lda + gc] : 0.f;
            *reinterpret_cast<float2*>(&As2[c][2 * r]) = make_float2(v, v);
        }
#pragma unroll
        for (int i = tid; i < BK * BN; i += 256) {
            int r = i / BN, c = i % BN;
            int gr = k0 + r, gc = bcol + c;
            Bs[r][c] = (gr < K && gc < N) ? B[gr * N + gc] : 0.f;
        }
        __syncthreads();
#pragma unroll
        for (int kk = 0; kk < BK; ++kk) {
            ulonglong2 aA = *reinterpret_cast<const ulonglong2*>(&As2[kk][ty * 8]);
            ulonglong2 aB = *reinterpret_cast<const ulonglong2*>(&As2[kk][ty * 8 + 4]);
            ulonglong2 bb = *reinterpret_cast<const ulonglong2*>(&Bs[kk][tx * 4]);
            acc[0][0] = fma2(aA.x, bb.x, acc[0][0]); acc[0][1] = fma2(aA.x, bb.y, acc[0][1]);
            acc[1][0] = fma2(aA.y, bb.x, acc[1][0]); acc[1][1] = fma2(aA.y, bb.y, acc[1][1]);
            acc[2][0] = fma2(aB.x, bb.x, acc[2][0]); acc[2][1] = fma2(aB.x, bb.y, acc[2][1]);
            acc[3][0] = fma2(aB.y, bb.x, acc[3][0]); acc[3][1] = fma2(aB.y, bb.y, acc[3][1]);
        }
        __syncthreads();
    }
#pragma unroll
    for (int i = 0; i < 4; ++i) {
        int row = brow + ty * 4 + i;
        if (row >= M) continue;
#pragma unroll
        for (int p = 0; p < 2; ++p) {
            float c0, c1;
            upk2(acc[i][p], c0, c1);
            int col0 = bcol + tx * 4 + 2 * p;
            if (col0 < N) {
                float v = c0 + bias[col0];
                if (SILU) v = v / (1.f + expf(-v));
                C[row * ldc + col0] = v;
            }
            if (col0 + 1 < N) {
                float v = c1 + bias[col0 + 1];
                if (SILU) v = v / (1.f + expf(-v));
                C[row * ldc + col0 + 1] = v;
            }
        }
    }
}

// ---------------- big GEMM (R9 version): 128x128 tile, TM=16 x TN=4, BK=8 ----------------
#define AS2_S 260
__global__ __launch_bounds__(256) void gemm128_kernel(
    const float* __restrict__ A, const float* __restrict__ B,
    const float* __restrict__ bias, float* __restrict__ C,
    int M, int N, int K, int lda, int ldc)
{
    __shared__ __align__(16) float As2[2][8][AS2_S];
    __shared__ __align__(16) float Bs[2][8][128];
    const int tid = threadIdx.x;
    const int tx = tid & 31, ty = tid >> 5;
    const int brow = blockIdx.y * 128, bcol = blockIdx.x * 128;

    const int ar = tid >> 1, ac4 = (tid & 1) * 4;
    const int br = tid >> 5, bc4 = (tid & 31) * 4;

    ull acc[16][2];
#pragma unroll
    for (int i = 0; i < 16; ++i) { acc[i][0] = 0ull; acc[i][1] = 0ull; }

    const int nk = K >> 3;

    float4 a_st;
    float b_st[4];
    {
        a_st = *reinterpret_cast<const float4*>(&A[(brow + ar) * lda + ac4]);
        int gcb = bcol + bc4;
#pragma unroll
        for (int j = 0; j < 4; ++j)
            b_st[j] = (gcb + j < N) ? B[br * N + gcb + j] : 0.f;
        float* ad = &As2[0][ac4][2 * ar];
        ad[0] = a_st.x; ad[1] = a_st.x;
        float* ad1 = &As2[0][ac4 + 1][2 * ar];
        ad1[0] = a_st.y; ad1[1] = a_st.y;
        float* ad2 = &As2[0][ac4 + 2][2 * ar];
        ad2[0] = a_st.z; ad2[1] = a_st.z;
        float* ad3 = &As2[0][ac4 + 3][2 * ar];
        ad3[0] = a_st.w; ad3[1] = a_st.w;
#pragma unroll
        for (int j = 0; j < 4; ++j) Bs[0][br][bc4 + j] = b_st[j];
    }
    __syncthreads();

    for (int kb = 0; kb < nk; ++kb) {
        int cur = kb & 1;
        if (kb + 1 < nk) {
            int k0 = (kb + 1) * 8;
            a_st = *reinterpret_cast<const float4*>(&A[(brow + ar) * lda + k0 + ac4]);
            int gcb = bcol + bc4;
#pragma unroll
            for (int j = 0; j < 4; ++j)
                b_st[j] = (gcb + j < N) ? B[(k0 + br) * N + gcb + j] : 0.f;
        }
#pragma unroll
        for (int kk = 0; kk < 8; ++kk) {
            const ulonglong2* ap = reinterpret_cast<const ulonglong2*>(&As2[cur][kk][ty * 32]);
            ulonglong2 bb = *reinterpret_cast<const ulonglong2*>(&Bs[cur][kk][tx * 4]);
            ull bx = bb.x, by = bb.y;
#pragma unroll
            for (int m = 0; m < 8; ++m) {
                ulonglong2 aa = ap[m];
                acc[2 * m][0]     = fma2(aa.x, bx, acc[2 * m][0]);
                acc[2 * m][1]     = fma2(aa.x, by, acc[2 * m][1]);
                acc[2 * m + 1][0] = fma2(aa.y, bx, acc[2 * m + 1][0]);
                acc[2 * m + 1][1] = fma2(aa.y, by, acc[2 * m + 1][1]);
            }
        }
        if (kb + 1 < nk) {
            int nxt = (kb + 1) & 1;
            float* ad = &As2[nxt][ac4][2 * ar];
            ad[0] = a_st.x; ad[1] = a_st.x;
            float* ad1 = &As2[nxt][ac4 + 1][2 * ar];
            ad1[0] = a_st.y; ad1[1] = a_st.y;
            float* ad2 = &As2[nxt][ac4 + 2][2 * ar];
            ad2[0] = a_st.z; ad2[1] = a_st.z;
            float* ad3 = &As2[nxt][ac4 + 3][2 * ar];
            ad3[0] = a_st.w; ad3[1] = a_st.w;
#pragma unroll
            for (int j = 0; j < 4; ++j) Bs[nxt][br][bc4 + j] = b_st[j];
        }
        __syncthreads();
    }

#pragma unroll
    for (int rr = 0; rr < 16; ++rr) {
        int row = brow + ty * 16 + rr;
#pragma unroll
        for (int p = 0; p < 2; ++p) {
            float c0, c1;
            upk2(acc[rr][p], c0, c1);
            int col0 = bcol + tx * 4 + 2 * p;
            if (col0 < N)     C[row * ldc + col0]     = c0 + bias[col0];
            if (col0 + 1 < N) C[row * ldc + col0 + 1] = c1 + bias[col0 + 1];
        }
    }
}

// ---------------- quantum kernel v5: RMT lambda, broadcast matvec ----------------
__device__ __forceinline__ int spread6(int v) {
    return (v & 1) | ((v & 2) << 1) | ((v & 4) << 2) | ((v & 8) << 3) |
           ((v & 16) << 4) | ((v & 32) << 5);
}

__device__ __forceinline__ void pauli_coef_raw(int x, int z, const float* __restrict__ th,
                                               float& cr, float& ci)
{
    if ((x | z) == 0) { cr = 0.f; ci = 0.f; return; }
    int idx4 = spread6(x ^ z) | (spread6(z) << 1);
    float v = __ldg(th + idx4 - 1);
    int p = __popc(x & z) & 3;               // (-i)^p
    cr = (p == 0) ? v : ((p == 2) ? -v : 0.f);
    ci = (p == 1) ? -v : ((p == 3) ? v : 0.f);
}

#define PHASEA() do {                                                              \
    const float4* _vp = reinterpret_cast<const float4*>(&vv[buf][slice * 8]);      \
    float4 _a0 = _vp[0], _a1 = _vp[1];                                             \
    float _pr0, _pi0, _pr1, _pi1;                                                  \
    _pr0 = hr[0] * _a0.x - hi[0] * _a0.y;  _pi0 = hr[0] * _a0.y + hi[0] * _a0.x;   \
    _pr1 = hr[1] * _a0.z - hi[1] * _a0.w;  _pi1 = hr[1] * _a0.w + hi[1] * _a0.z;   \
    _pr0 += hr[2] * _a1.x - hi[2] * _a1.y; _pi0 += hr[2] * _a1.y + hi[2] * _a1.x;  \
    _pr1 += hr[3] * _a1.z - hi[3] * _a1.w; _pi1 += hr[3] * _a1.w + hi[3] * _a1.z;  \
    float4 _a2 = _vp[2], _a3 = _vp[3];                                             \
    _pr0 += hr[4] * _a2.x - hi[4] * _a2.y; _pi0 += hr[4] * _a2.y + hi[4] * _a2.x;  \
    _pr1 += hr[5] * _a2.z - hi[5] * _a2.w; _pi1 += hr[5] * _a2.w + hi[5] * _a2.z;  \
    _pr0 += hr[6] * _a3.x - hi[6] * _a3.y; _pi0 += hr[6] * _a3.y + hi[6] * _a3.x;  \
    _pr1 += hr[7] * _a3.z - hi[7] * _a3.w; _pi1 += hr[7] * _a3.w + hi[7] * _a3.z;  \
    spart[slice * 64 + row] = make_float2(_pr0 + _pr1, _pi0 + _pi1);               \
} while (0)

__global__ __launch_bounds__(512, 3) void quantum_kernel(
    const float* __restrict__ theta_all,
    const float* __restrict__ Aoff, const float* __restrict__ Boff,
    const float* __restrict__ Ddiag,
    const float* __restrict__ Wv1, const float* __restrict__ bv1,
    float* __restrict__ hid2_out)
{
    const int b = blockIdx.x;
    const float* th = theta_all + b * THETA_STRIDE;
    const int t = threadIdx.x;
    const int lane = t & 31, warp = t >> 5;

    __shared__ float sHr[64 * 65];
    __shared__ float sHi[64 * 65];
    __shared__ __align__(16) float2 vv[2][64];
    __shared__ __align__(16) float2 spart[512];
    __shared__ float spr[64], spi[64];
    __shared__ float sJ[128];
    __shared__ float s_sin[128];
    __shared__ float sred[16];
    __shared__ float s_scl[4];
    __shared__ float sq[16];
    __shared__ int s_K;

    // --- sum theta^2 -> lambda_F ---
    float ss = 0.f;
    for (int m = t; m < NGEN; m += 512) { float v = __ldg(th + m); ss += v * v; }
#pragma unroll
    for (int d = 16; d; d >>= 1) ss += __shfl_xor_sync(0xffffffffu, ss, d);
    if (lane == 0) sred[warp] = ss;

    // --- quadrature sin table (128-pt) ---
    if (t < 128) s_sin[t] = __sinf((float)t * 0.049087385212f);  // 2*pi/128

    // --- build raw H via 64-pt WHT per x-mask (16 warps -> 4 passes) ---
    for (int pass = 0; pass < 4; ++pass) {
        int x = pass * 16 + warp;
        float ar, ai, br, bi;
        pauli_coef_raw(x, lane, th, ar, ai);
        pauli_coef_raw(x, lane + 32, th, br, bi);
        float t0r = ar + br, t0i = ai + bi;
        float t1r = ar - br, t1i = ai - bi;
#pragma unroll
        for (int d = 16; d >= 1; d >>= 1) {
            float o;
            o = __shfl_xor_sync(0xffffffffu, t0r, d); t0r = (lane & d) ? (o - t0r) : (t0r + o);
            o = __shfl_xor_sync(0xffffffffu, t0i, d); t0i = (lane & d) ? (o - t0i) : (t0i + o);
            o = __shfl_xor_sync(0xffffffffu, t1r, d); t1r = (lane & d) ? (o - t1r) : (t1r + o);
            o = __shfl_xor_sync(0xffffffffu, t1i, d); t1i = (lane & d) ? (o - t1i) : (t1i + o);
        }
        sHr[lane * 65 + (lane ^ x)] = t0r;
        sHi[lane * 65 + (lane ^ x)] = t0i;
        int r2 = lane + 32;
        sHr[r2 * 65 + (r2 ^ x)] = t1r;
        sHi[r2 * 65 + (r2 ^ x)] = t1i;
    }
    __syncthreads();

    // --- stage H slice: row = t&63, slice = t>>6 ---
    const int row = t & 63, slice = t >> 6, cb = slice * 8;
    float hr[8], hi[8];
#pragma unroll
    for (int j = 0; j < 8; ++j) {
        hr[j] = sHr[row * 65 + cb + j];
        hi[j] = sHi[row * 65 + cb + j];
    }

    // --- RMT lambda + K (thread 0), e0 init ---
    if (t == 0) {
        float tot = 0.f;
#pragma unroll
        for (int i = 0; i < 16; ++i) tot += sred[i];
        float lamF = sqrtf(64.f * fmaxf(tot, 1e-12f));
        float lu = fmaxf(0.285f * lamF, 1e-3f);
        int K = (int)ceilf(lu + 3.0f * cbrtf(lu) + 2.f);
        if (K < 6) K = 6;
        if (K > 99) K = 99;
        s_scl[0] = lu;
        s_scl[1] = 1.f / lu;
        s_K = K;
    }
    if (t < 64) vv[0][t] = make_float2((t == 0) ? 1.f : 0.f, 0.f);
    __syncthreads();
    const float invl = s_scl[1];
    const int K = s_K;

    // --- Bessel J_k via 128-pt DFT quadrature ---
    if (t < 128) s_sin[t] *= s_scl[0];
    __syncthreads();
    {
        int k = t >> 2, jb = t & 3;
        const float C0 = 0.049087385212f;  // 2*pi/128
        int idx = (k * jb) & 127;
        int step = (4 * k) & 127;
        float sum = 0.f;
        int j = jb;
#pragma unroll 8
        for (int i = 0; i < 32; ++i) {
            float ang = fmaf((float)idx, C0, -s_sin[j]);
            sum += __cosf(ang);
            idx = (idx + step) & 127;
            j += 4;
        }
        sum += __shfl_xor_sync(0xffffffffu, sum, 1);
        sum += __shfl_xor_sync(0xffffffffu, sum, 2);
        if (jb == 0) sJ[k] = sum * (1.f / 128.f);
    }
    __syncthreads();

    // --- Chebyshev: psi = sum c_k T_k(H/lu) e0 ---
    int buf = 0;
    float cur_r = 0.f, cur_i = 0.f, prev_r = 0.f, prev_i = 0.f;
    float psi_r = 0.f, psi_i = 0.f;
    if (t < 64) {
        cur_r = (t == 0) ? 1.f : 0.f;
        psi_r = sJ[0] * cur_r;
    }

    for (int k = 1; k <= K; ++k) {
        PHASEA();
        __syncthreads();
        if (t < 64) {
            float ar = 0.f, ai = 0.f;
#pragma unroll
            for (int s = 0; s < 8; ++s) {
                float2 p = spart[s * 64 + t];
                ar += p.x; ai += p.y;
            }
            ar *= invl; ai *= invl;
            float tnr, tni;
            if (k == 1) { tnr = ar; tni = ai; }
            else        { tnr = 2.f * ar - prev_r; tni = 2.f * ai - prev_i; }
            float cj = 2.f * sJ[k];
            switch (k & 3) {
                case 0: psi_r += cj * tnr; psi_i += cj * tni; break;
                case 1: psi_r -= cj * tni; psi_i += cj * tnr; break;
                case 2: psi_r -= cj * tnr; psi_i -= cj * tni; break;
                case 3: psi_r += cj * tni; psi_i -= cj * tnr; break;
            }
            prev_r = cur_r; prev_i = cur_i;
            cur_r = tnr;    cur_i = tni;
            vv[buf ^ 1][t] = make_float2(tnr, tni);
        }
        __syncthreads();
        buf ^= 1;
    }
    if (t < 64) { spr[t] = psi_r; spi[t] = psi_i; }

    // --- renormalize |psi> ---
    {
        float n = (t < 64) ? (psi_r * psi_r + psi_i * psi_i) : 0.f;
#pragma unroll
        for (int d = 16; d; d >>= 1) n += __shfl_xor_sync(0xffffffffu, n, d);
        if (lane == 0) sred[warp] = n;
        __syncthreads();
        if (t == 0) {
            float tot = sred[0] + sred[1];
            s_scl[2] = 1.f / fmaxf(tot, 1e-30f);
        }
        __syncthreads();
    }

    // --- 15 two-local observables -> sq ---
    if (t < NOBS) {
        const int wa[15] = {0,0,0,0,0,1,1,1,1,2,2,2,3,3,4};
        const int wb[15] = {1,2,3,4,5,2,3,4,5,3,4,5,4,5,5};
        int a = wa[t], bq = wb[t];
        int pa = 5 - a, pb = 5 - bq;
        float Hd[4];
        Hd[0] = 2.f * __ldg(Ddiag + t * 4 + 1);
        Hd[1] = 2.f * __ldg(Ddiag + t * 4 + 2);
        Hd[2] = 2.f * __ldg(Ddiag + t * 4 + 3);
        Hd[3] = 0.f;
        float Ac[6], Bc[6];
#pragma unroll
        for (int c = 0; c < 6; ++c) {
            Ac[c] = __ldg(Aoff + t * 6 + c);
            Bc[c] = __ldg(Boff + t * 6 + c);
        }
        const int kk_[6] = {1, 2, 2, 3, 3, 3};
        const int ll_[6] = {0, 0, 1, 0, 1, 2};
        float q = 0.f;
        for (int r = 0; r < 16; ++r) {
            int idx0 = 0, rr = r;
#pragma unroll
            for (int p = 0; p < 6; ++p) {
                if (p != pa && p != pb) { idx0 |= (rr & 1) << p; rr >>= 1; }
            }
            float xr[4], xi[4];
#pragma unroll
            for (int k = 0; k < 4; ++k) {
                int idx = idx0 | (((k >> 1) & 1) << pa) | ((k & 1) << pb);
                xr[k] = spr[idx]; xi[k] = spi[idx];
            }
#pragma unroll
            for (int k = 0; k < 4; ++k) q += Hd[k] * (xr[k] * xr[k] + xi[k] * xi[k]);
#pragma unroll
            for (int c = 0; c < 6; ++c) {
                int k = kk_[c], l = ll_[c];
                float rr2 = xr[k] * xr[l] + xi[k] * xi[l];
                float ii2 = xi[k] * xr[l] - xr[k] * xi[l];
                q += 2.f * (Ac[c] * rr2 + Bc[c] * ii2);
            }
        }
        sq[t] = q * s_scl[2];
    }
    __syncthreads();

    // --- fused vel-head layer 1 (first 256 threads) ---
    if (t < HID) {
        float h = __ldg(bv1 + t);
#pragma unroll
        for (int o = 0; o < NOBS; ++o) h = fmaf(sq[o], __ldg(Wv1 + o * HID + t), h);
        h = h / (1.f + expf(-h));
        hid2_out[b * HID + t] = h;
    }
}

// ---------------- launch ----------------
extern "C" void kernel_launch(void* const* d_in, const int* in_sizes, int n_in,
                              void* d_out, int out_size)
{
    const float* x    = (const float*)d_in[0];
    const float* W1   = (const float*)d_in[1];
    const float* b1   = (const float*)d_in[2];
    const float* W2   = (const float*)d_in[3];
    const float* b2   = (const float*)d_in[4];
    const float* Aoff = (const float*)d_in[5];
    const float* Boff = (const float*)d_in[6];
    const float* Dd   = (const float*)d_in[7];
    const float* Wv1  = (const float*)d_in[8];
    const float* bv1  = (const float*)d_in[9];
    const float* Wv2  = (const float*)d_in[10];
    const float* bv2  = (const float*)d_in[11];
    float* out = (float*)d_out;

    float* hid;   cudaGetSymbolAddress((void**)&hid,   g_hid);
    float* theta; cudaGetSymbolAddress((void**)&theta, g_theta);
    float* hid2;  cudaGetSymbolAddress((void**)&hid2,  g_hid2);

    {
        dim3 g((HID + 63) / 64, (BATCH + 63) / 64);
        gemm_kernel<true><<<g, 256>>>(x, W1, b1, hid, BATCH, HID, INDIM, INDIM, HID);
    }
    {
        dim3 g((NGEN + 127) / 128, (BATCH + 127) / 128);
        gemm128_kernel<<<g, 256>>>(hid, W2, b2, theta, BATCH, NGEN, HID, HID, THETA_STRIDE);
    }
    quantum_kernel<<<BATCH, 512>>>(theta, Aoff, Boff, Dd, Wv1, bv1, hid2);
    // no dummies: my 4th launch = g4 (the only unmeasured kernel) -> ncu captures it
    {
        dim3 g((CHUNK + 63) / 64, (BATCH + 63) / 64);
        gemm_kernel<false><<<g, 256>>>(hid2, Wv2, bv2, out, BATCH, CHUNK, HID, HID, CHUNK);
    }
}

// round 14
// speedup vs baseline: 1.7570x; 1.6104x over previous
#include <cuda_runtime.h>
#include <math.h>

#define BATCH 512
#define NGEN 4095
#define THETA_STRIDE 4096
#define HID 256
#define INDIM 768
#define CHUNK 512
#define NOBS 15

typedef unsigned long long ull;

// ---------------- f32x2 packed helpers (Blackwell) ----------------
__device__ __forceinline__ ull pk2(float lo, float hi) {
    ull r; asm("mov.b64 %0, {%1, %2};" : "=l"(r) : "f"(lo), "f"(hi)); return r;
}
__device__ __forceinline__ void upk2(ull v, float& lo, float& hi) {
    asm("mov.b64 {%0, %1}, %2;" : "=f"(lo), "=f"(hi) : "l"(v));
}
__device__ __forceinline__ ull fma2(ull a, ull b, ull c) {
    ull d; asm("fma.rn.f32x2 %0, %1, %2, %3;" : "=l"(d) : "l"(a), "l"(b), "l"(c)); return d;
}

// ---------------- scratch ----------------
__device__ float g_hid[BATCH * HID];
__device__ float g_theta[BATCH * THETA_STRIDE];
__device__ float g_hid2[BATCH * HID];

// ---------------- small GEMM v2: 64x64 tile, BK=16, double-buffered prefetch ----------------
// Exact-tile assumption: 64|M, 64|N, 16|K (holds for all call sites).
#define SA_S 132   // padded A row stride (words): conflict-free STS, 16B-aligned rows
#define SB_S 68    // padded B row stride
template <bool SILU>
__global__ __launch_bounds__(256) void gemm_kernel(
    const float* __restrict__ A, const float* __restrict__ B,
    const float* __restrict__ bias, float* __restrict__ C,
    int M, int N, int K, int lda, int ldc)
{
    __shared__ __align__(16) float As2[2][16][SA_S];   // duplicated (a,a) pairs
    __shared__ __align__(16) float Bs[2][16][SB_S];
    const int tid = threadIdx.x;
    const int tx = tid % 16, ty = tid / 16;
    const int brow = blockIdx.y * 64, bcol = blockIdx.x * 64;

    const int ar = tid >> 2, ac4 = (tid & 3) * 4;      // A: float4 at (row ar, cols ac4..+3)
    const int br = tid >> 4, bc4 = (tid & 15) * 4;     // B: float4 at (row br, cols bc4..+3)

    ull acc[4][2];
#pragma unroll
    for (int i = 0; i < 4; ++i) { acc[i][0] = 0ull; acc[i][1] = 0ull; }

    const int nk = K >> 4;

    float4 a_st = *reinterpret_cast<const float4*>(&A[(brow + ar) * lda + ac4]);
    float4 b_st = *reinterpret_cast<const float4*>(&B[br * N + bcol + bc4]);

    // store tile 0
    {
        float2* p0 = reinterpret_cast<float2*>(&As2[0][ac4][2 * ar]);
        float2* p1 = reinterpret_cast<float2*>(&As2[0][ac4 + 1][2 * ar]);
        float2* p2 = reinterpret_cast<float2*>(&As2[0][ac4 + 2][2 * ar]);
        float2* p3 = reinterpret_cast<float2*>(&As2[0][ac4 + 3][2 * ar]);
        *p0 = make_float2(a_st.x, a_st.x);
        *p1 = make_float2(a_st.y, a_st.y);
        *p2 = make_float2(a_st.z, a_st.z);
        *p3 = make_float2(a_st.w, a_st.w);
        *reinterpret_cast<float4*>(&Bs[0][br][bc4]) = b_st;
    }
    __syncthreads();

    for (int kb = 0; kb < nk; ++kb) {
        int cur = kb & 1;
        if (kb + 1 < nk) {
            int k0 = (kb + 1) * 16;
            a_st = *reinterpret_cast<const float4*>(&A[(brow + ar) * lda + k0 + ac4]);
            b_st = *reinterpret_cast<const float4*>(&B[(k0 + br) * N + bcol + bc4]);
        }
#pragma unroll
        for (int kk = 0; kk < 16; ++kk) {
            ulonglong2 aA = *reinterpret_cast<const ulonglong2*>(&As2[cur][kk][ty * 8]);
            ulonglong2 aB = *reinterpret_cast<const ulonglong2*>(&As2[cur][kk][ty * 8 + 4]);
            ulonglong2 bb = *reinterpret_cast<const ulonglong2*>(&Bs[cur][kk][tx * 4]);
            acc[0][0] = fma2(aA.x, bb.x, acc[0][0]); acc[0][1] = fma2(aA.x, bb.y, acc[0][1]);
            acc[1][0] = fma2(aA.y, bb.x, acc[1][0]); acc[1][1] = fma2(aA.y, bb.y, acc[1][1]);
            acc[2][0] = fma2(aB.x, bb.x, acc[2][0]); acc[2][1] = fma2(aB.x, bb.y, acc[2][1]);
            acc[3][0] = fma2(aB.y, bb.x, acc[3][0]); acc[3][1] = fma2(aB.y, bb.y, acc[3][1]);
        }
        if (kb + 1 < nk) {
            int nxt = (kb + 1) & 1;
            float2* p0 = reinterpret_cast<float2*>(&As2[nxt][ac4][2 * ar]);
            float2* p1 = reinterpret_cast<float2*>(&As2[nxt][ac4 + 1][2 * ar]);
            float2* p2 = reinterpret_cast<float2*>(&As2[nxt][ac4 + 2][2 * ar]);
            float2* p3 = reinterpret_cast<float2*>(&As2[nxt][ac4 + 3][2 * ar]);
            *p0 = make_float2(a_st.x, a_st.x);
            *p1 = make_float2(a_st.y, a_st.y);
            *p2 = make_float2(a_st.z, a_st.z);
            *p3 = make_float2(a_st.w, a_st.w);
            *reinterpret_cast<float4*>(&Bs[nxt][br][bc4]) = b_st;
        }
        __syncthreads();
    }

#pragma unroll
    for (int i = 0; i < 4; ++i) {
        int row = brow + ty * 4 + i;
#pragma unroll
        for (int p = 0; p < 2; ++p) {
            float c0, c1;
            upk2(acc[i][p], c0, c1);
            int col0 = bcol + tx * 4 + 2 * p;
            float v0 = c0 + bias[col0];
            float v1 = c1 + bias[col0 + 1];
            if (SILU) {
                v0 = v0 / (1.f + expf(-v0));
                v1 = v1 / (1.f + expf(-v1));
            }
            C[row * ldc + col0]     = v0;
            C[row * ldc + col0 + 1] = v1;
        }
    }
}

// ---------------- big GEMM (R9 version): 128x128 tile, TM=16 x TN=4, BK=8 ----------------
#define AS2_S 260
__global__ __launch_bounds__(256) void gemm128_kernel(
    const float* __restrict__ A, const float* __restrict__ B,
    const float* __restrict__ bias, float* __restrict__ C,
    int M, int N, int K, int lda, int ldc)
{
    __shared__ __align__(16) float As2[2][8][AS2_S];
    __shared__ __align__(16) float Bs[2][8][128];
    const int tid = threadIdx.x;
    const int tx = tid & 31, ty = tid >> 5;
    const int brow = blockIdx.y * 128, bcol = blockIdx.x * 128;

    const int ar = tid >> 1, ac4 = (tid & 1) * 4;
    const int br = tid >> 5, bc4 = (tid & 31) * 4;

    ull acc[16][2];
#pragma unroll
    for (int i = 0; i < 16; ++i) { acc[i][0] = 0ull; acc[i][1] = 0ull; }

    const int nk = K >> 3;

    float4 a_st;
    float b_st[4];
    {
        a_st = *reinterpret_cast<const float4*>(&A[(brow + ar) * lda + ac4]);
        int gcb = bcol + bc4;
#pragma unroll
        for (int j = 0; j < 4; ++j)
            b_st[j] = (gcb + j < N) ? B[br * N + gcb + j] : 0.f;
        float* ad = &As2[0][ac4][2 * ar];
        ad[0] = a_st.x; ad[1] = a_st.x;
        float* ad1 = &As2[0][ac4 + 1][2 * ar];
        ad1[0] = a_st.y; ad1[1] = a_st.y;
        float* ad2 = &As2[0][ac4 + 2][2 * ar];
        ad2[0] = a_st.z; ad2[1] = a_st.z;
        float* ad3 = &As2[0][ac4 + 3][2 * ar];
        ad3[0] = a_st.w; ad3[1] = a_st.w;
#pragma unroll
        for (int j = 0; j < 4; ++j) Bs[0][br][bc4 + j] = b_st[j];
    }
    __syncthreads();

    for (int kb = 0; kb < nk; ++kb) {
        int cur = kb & 1;
        if (kb + 1 < nk) {
            int k0 = (kb + 1) * 8;
            a_st = *reinterpret_cast<const float4*>(&A[(brow + ar) * lda + k0 + ac4]);
            int gcb = bcol + bc4;
#pragma unroll
            for (int j = 0; j < 4; ++j)
                b_st[j] = (gcb + j < N) ? B[(k0 + br) * N + gcb + j] : 0.f;
        }
#pragma unroll
        for (int kk = 0; kk < 8; ++kk) {
            const ulonglong2* ap = reinterpret_cast<const ulonglong2*>(&As2[cur][kk][ty * 32]);
            ulonglong2 bb = *reinterpret_cast<const ulonglong2*>(&Bs[cur][kk][tx * 4]);
            ull bx = bb.x, by = bb.y;
#pragma unroll
            for (int m = 0; m < 8; ++m) {
                ulonglong2 aa = ap[m];
                acc[2 * m][0]     = fma2(aa.x, bx, acc[2 * m][0]);
                acc[2 * m][1]     = fma2(aa.x, by, acc[2 * m][1]);
                acc[2 * m + 1][0] = fma2(aa.y, bx, acc[2 * m + 1][0]);
                acc[2 * m + 1][1] = fma2(aa.y, by, acc[2 * m + 1][1]);
            }
        }
        if (kb + 1 < nk) {
            int nxt = (kb + 1) & 1;
            float* ad = &As2[nxt][ac4][2 * ar];
            ad[0] = a_st.x; ad[1] = a_st.x;
            float* ad1 = &As2[nxt][ac4 + 1][2 * ar];
            ad1[0] = a_st.y; ad1[1] = a_st.y;
            float* ad2 = &As2[nxt][ac4 + 2][2 * ar];
            ad2[0] = a_st.z; ad2[1] = a_st.z;
            float* ad3 = &As2[nxt][ac4 + 3][2 * ar];
            ad3[0] = a_st.w; ad3[1] = a_st.w;
#pragma unroll
            for (int j = 0; j < 4; ++j) Bs[nxt][br][bc4 + j] = b_st[j];
        }
        __syncthreads();
    }

#pragma unroll
    for (int rr = 0; rr < 16; ++rr) {
        int row = brow + ty * 16 + rr;
#pragma unroll
        for (int p = 0; p < 2; ++p) {
            float c0, c1;
            upk2(acc[rr][p], c0, c1);
            int col0 = bcol + tx * 4 + 2 * p;
            if (col0 < N)     C[row * ldc + col0]     = c0 + bias[col0];
            if (col0 + 1 < N) C[row * ldc + col0 + 1] = c1 + bias[col0 + 1];
        }
    }
}

// ---------------- quantum kernel v5: RMT lambda, broadcast matvec ----------------
__device__ __forceinline__ int spread6(int v) {
    return (v & 1) | ((v & 2) << 1) | ((v & 4) << 2) | ((v & 8) << 3) |
           ((v & 16) << 4) | ((v & 32) << 5);
}

__device__ __forceinline__ void pauli_coef_raw(int x, int z, const float* __restrict__ th,
                                               float& cr, float& ci)
{
    if ((x | z) == 0) { cr = 0.f; ci = 0.f; return; }
    int idx4 = spread6(x ^ z) | (spread6(z) << 1);
    float v = __ldg(th + idx4 - 1);
    int p = __popc(x & z) & 3;               // (-i)^p
    cr = (p == 0) ? v : ((p == 2) ? -v : 0.f);
    ci = (p == 1) ? -v : ((p == 3) ? v : 0.f);
}

#define PHASEA() do {                                                              \
    const float4* _vp = reinterpret_cast<const float4*>(&vv[buf][slice * 8]);      \
    float4 _a0 = _vp[0], _a1 = _vp[1];                                             \
    float _pr0, _pi0, _pr1, _pi1;                                                  \
    _pr0 = hr[0] * _a0.x - hi[0] * _a0.y;  _pi0 = hr[0] * _a0.y + hi[0] * _a0.x;   \
    _pr1 = hr[1] * _a0.z - hi[1] * _a0.w;  _pi1 = hr[1] * _a0.w + hi[1] * _a0.z;   \
    _pr0 += hr[2] * _a1.x - hi[2] * _a1.y; _pi0 += hr[2] * _a1.y + hi[2] * _a1.x;  \
    _pr1 += hr[3] * _a1.z - hi[3] * _a1.w; _pi1 += hr[3] * _a1.w + hi[3] * _a1.z;  \
    float4 _a2 = _vp[2], _a3 = _vp[3];                                             \
    _pr0 += hr[4] * _a2.x - hi[4] * _a2.y; _pi0 += hr[4] * _a2.y + hi[4] * _a2.x;  \
    _pr1 += hr[5] * _a2.z - hi[5] * _a2.w; _pi1 += hr[5] * _a2.w + hi[5] * _a2.z;  \
    _pr0 += hr[6] * _a3.x - hi[6] * _a3.y; _pi0 += hr[6] * _a3.y + hi[6] * _a3.x;  \
    _pr1 += hr[7] * _a3.z - hi[7] * _a3.w; _pi1 += hr[7] * _a3.w + hi[7] * _a3.z;  \
    spart[slice * 64 + row] = make_float2(_pr0 + _pr1, _pi0 + _pi1);               \
} while (0)

__global__ __launch_bounds__(512, 3) void quantum_kernel(
    const float* __restrict__ theta_all,
    const float* __restrict__ Aoff, const float* __restrict__ Boff,
    const float* __restrict__ Ddiag,
    const float* __restrict__ Wv1, const float* __restrict__ bv1,
    float* __restrict__ hid2_out)
{
    const int b = blockIdx.x;
    const float* th = theta_all + b * THETA_STRIDE;
    const int t = threadIdx.x;
    const int lane = t & 31, warp = t >> 5;

    __shared__ float sHr[64 * 65];
    __shared__ float sHi[64 * 65];
    __shared__ __align__(16) float2 vv[2][64];
    __shared__ __align__(16) float2 spart[512];
    __shared__ float spr[64], spi[64];
    __shared__ float sJ[128];
    __shared__ float s_sin[128];
    __shared__ float sred[16];
    __shared__ float s_scl[4];
    __shared__ float sq[16];
    __shared__ int s_K;

    // --- sum theta^2 -> lambda_F ---
    float ss = 0.f;
    for (int m = t; m < NGEN; m += 512) { float v = __ldg(th + m); ss += v * v; }
#pragma unroll
    for (int d = 16; d; d >>= 1) ss += __shfl_xor_sync(0xffffffffu, ss, d);
    if (lane == 0) sred[warp] = ss;

    // --- quadrature sin table (128-pt) ---
    if (t < 128) s_sin[t] = __sinf((float)t * 0.049087385212f);  // 2*pi/128

    // --- build raw H via 64-pt WHT per x-mask (16 warps -> 4 passes) ---
    for (int pass = 0; pass < 4; ++pass) {
        int x = pass * 16 + warp;
        float ar, ai, br, bi;
        pauli_coef_raw(x, lane, th, ar, ai);
        pauli_coef_raw(x, lane + 32, th, br, bi);
        float t0r = ar + br, t0i = ai + bi;
        float t1r = ar - br, t1i = ai - bi;
#pragma unroll
        for (int d = 16; d >= 1; d >>= 1) {
            float o;
            o = __shfl_xor_sync(0xffffffffu, t0r, d); t0r = (lane & d) ? (o - t0r) : (t0r + o);
            o = __shfl_xor_sync(0xffffffffu, t0i, d); t0i = (lane & d) ? (o - t0i) : (t0i + o);
            o = __shfl_xor_sync(0xffffffffu, t1r, d); t1r = (lane & d) ? (o - t1r) : (t1r + o);
            o = __shfl_xor_sync(0xffffffffu, t1i, d); t1i = (lane & d) ? (o - t1i) : (t1i + o);
        }
        sHr[lane * 65 + (lane ^ x)] = t0r;
        sHi[lane * 65 + (lane ^ x)] = t0i;
        int r2 = lane + 32;
        sHr[r2 * 65 + (r2 ^ x)] = t1r;
        sHi[r2 * 65 + (r2 ^ x)] = t1i;
    }
    __syncthreads();

    // --- stage H slice: row = t&63, slice = t>>6 ---
    const int row = t & 63, slice = t >> 6, cb = slice * 8;
    float hr[8], hi[8];
#pragma unroll
    for (int j = 0; j < 8; ++j) {
        hr[j] = sHr[row * 65 + cb + j];
        hi[j] = sHi[row * 65 + cb + j];
    }

    // --- RMT lambda + K (thread 0), e0 init ---
    if (t == 0) {
        float tot = 0.f;
#pragma unroll
        for (int i = 0; i < 16; ++i) tot += sred[i];
        float lamF = sqrtf(64.f * fmaxf(tot, 1e-12f));
        float lu = fmaxf(0.285f * lamF, 1e-3f);
        int K = (int)ceilf(lu + 3.0f * cbrtf(lu) + 2.f);
        if (K < 6) K = 6;
        if (K > 99) K = 99;
        s_scl[0] = lu;
        s_scl[1] = 1.f / lu;
        s_K = K;
    }
    if (t < 64) vv[0][t] = make_float2((t == 0) ? 1.f : 0.f, 0.f);
    __syncthreads();
    const float invl = s_scl[1];
    const int K = s_K;

    // --- Bessel J_k via 128-pt DFT quadrature ---
    if (t < 128) s_sin[t] *= s_scl[0];
    __syncthreads();
    {
        int k = t >> 2, jb = t & 3;
        const float C0 = 0.049087385212f;  // 2*pi/128
        int idx = (k * jb) & 127;
        int step = (4 * k) & 127;
        float sum = 0.f;
        int j = jb;
#pragma unroll 8
        for (int i = 0; i < 32; ++i) {
            float ang = fmaf((float)idx, C0, -s_sin[j]);
            sum += __cosf(ang);
            idx = (idx + step) & 127;
            j += 4;
        }
        sum += __shfl_xor_sync(0xffffffffu, sum, 1);
        sum += __shfl_xor_sync(0xffffffffu, sum, 2);
        if (jb == 0) sJ[k] = sum * (1.f / 128.f);
    }
    __syncthreads();

    // --- Chebyshev: psi = sum c_k T_k(H/lu) e0 ---
    int buf = 0;
    float cur_r = 0.f, cur_i = 0.f, prev_r = 0.f, prev_i = 0.f;
    float psi_r = 0.f, psi_i = 0.f;
    if (t < 64) {
        cur_r = (t == 0) ? 1.f : 0.f;
        psi_r = sJ[0] * cur_r;
    }

    for (int k = 1; k <= K; ++k) {
        PHASEA();
        __syncthreads();
        if (t < 64) {
            float ar = 0.f, ai = 0.f;
#pragma unroll
            for (int s = 0; s < 8; ++s) {
                float2 p = spart[s * 64 + t];
                ar += p.x; ai += p.y;
            }
            ar *= invl; ai *= invl;
            float tnr, tni;
            if (k == 1) { tnr = ar; tni = ai; }
            else        { tnr = 2.f * ar - prev_r; tni = 2.f * ai - prev_i; }
            float cj = 2.f * sJ[k];
            switch (k & 3) {
                case 0: psi_r += cj * tnr; psi_i += cj * tni; break;
                case 1: psi_r -= cj * tni; psi_i += cj * tnr; break;
                case 2: psi_r -= cj * tnr; psi_i -= cj * tni; break;
                case 3: psi_r += cj * tni; psi_i -= cj * tnr; break;
            }
            prev_r = cur_r; prev_i = cur_i;
            cur_r = tnr;    cur_i = tni;
            vv[buf ^ 1][t] = make_float2(tnr, tni);
        }
        __syncthreads();
        buf ^= 1;
    }
    if (t < 64) { spr[t] = psi_r; spi[t] = psi_i; }

    // --- renormalize |psi> ---
    {
        float n = (t < 64) ? (psi_r * psi_r + psi_i * psi_i) : 0.f;
#pragma unroll
        for (int d = 16; d; d >>= 1) n += __shfl_xor_sync(0xffffffffu, n, d);
        if (lane == 0) sred[warp] = n;
        __syncthreads();
        if (t == 0) {
            float tot = sred[0] + sred[1];
            s_scl[2] = 1.f / fmaxf(tot, 1e-30f);
        }
        __syncthreads();
    }

    // --- 15 two-local observables -> sq ---
    if (t < NOBS) {
        const int wa[15] = {0,0,0,0,0,1,1,1,1,2,2,2,3,3,4};
        const int wb[15] = {1,2,3,4,5,2,3,4,5,3,4,5,4,5,5};
        int a = wa[t], bq = wb[t];
        int pa = 5 - a, pb = 5 - bq;
        float Hd[4];
        Hd[0] = 2.f * __ldg(Ddiag + t * 4 + 1);
        Hd[1] = 2.f * __ldg(Ddiag + t * 4 + 2);
        Hd[2] = 2.f * __ldg(Ddiag + t * 4 + 3);
        Hd[3] = 0.f;
        float Ac[6], Bc[6];
#pragma unroll
        for (int c = 0; c < 6; ++c) {
            Ac[c] = __ldg(Aoff + t * 6 + c);
            Bc[c] = __ldg(Boff + t * 6 + c);
        }
        const int kk_[6] = {1, 2, 2, 3, 3, 3};
        const int ll_[6] = {0, 0, 1, 0, 1, 2};
        float q = 0.f;
        for (int r = 0; r < 16; ++r) {
            int idx0 = 0, rr = r;
#pragma unroll
            for (int p = 0; p < 6; ++p) {
                if (p != pa && p != pb) { idx0 |= (rr & 1) << p; rr >>= 1; }
            }
            float xr[4], xi[4];
#pragma unroll
            for (int k = 0; k < 4; ++k) {
                int idx = idx0 | (((k >> 1) & 1) << pa) | ((k & 1) << pb);
                xr[k] = spr[idx]; xi[k] = spi[idx];
            }
#pragma unroll
            for (int k = 0; k < 4; ++k) q += Hd[k] * (xr[k] * xr[k] + xi[k] * xi[k]);
#pragma unroll
            for (int c = 0; c < 6; ++c) {
                int k = kk_[c], l = ll_[c];
                float rr2 = xr[k] * xr[l] + xi[k] * xi[l];
                float ii2 = xi[k] * xr[l] - xr[k] * xi[l];
                q += 2.f * (Ac[c] * rr2 + Bc[c] * ii2);
            }
        }
        sq[t] = q * s_scl[2];
    }
    __syncthreads();

    // --- fused vel-head layer 1 (first 256 threads) ---
    if (t < HID) {
        float h = __ldg(bv1 + t);
#pragma unroll
        for (int o = 0; o < NOBS; ++o) h = fmaf(sq[o], __ldg(Wv1 + o * HID + t), h);
        h = h / (1.f + expf(-h));
        hid2_out[b * HID + t] = h;
    }
}

// ---------------- launch ----------------
extern "C" void kernel_launch(void* const* d_in, const int* in_sizes, int n_in,
                              void* d_out, int out_size)
{
    const float* x    = (const float*)d_in[0];
    const float* W1   = (const float*)d_in[1];
    const float* b1   = (const float*)d_in[2];
    const float* W2   = (const float*)d_in[3];
    const float* b2   = (const float*)d_in[4];
    const float* Aoff = (const float*)d_in[5];
    const float* Boff = (const float*)d_in[6];
    const float* Dd   = (const float*)d_in[7];
    const float* Wv1  = (const float*)d_in[8];
    const float* bv1  = (const float*)d_in[9];
    const float* Wv2  = (const float*)d_in[10];
    const float* bv2  = (const float*)d_in[11];
    float* out = (float*)d_out;

    float* hid;   cudaGetSymbolAddress((void**)&hid,   g_hid);
    float* theta; cudaGetSymbolAddress((void**)&theta, g_theta);
    float* hid2;  cudaGetSymbolAddress((void**)&hid2,  g_hid2);

    {
        dim3 g(HID / 64, BATCH / 64);
        gemm_kernel<true><<<g, 256>>>(x, W1, b1, hid, BATCH, HID, INDIM, INDIM, HID);
    }
    {
        dim3 g((NGEN + 127) / 128, (BATCH + 127) / 128);
        gemm128_kernel<<<g, 256>>>(hid, W2, b2, theta, BATCH, NGEN, HID, HID, THETA_STRIDE);
    }
    quantum_kernel<<<BATCH, 512>>>(theta, Aoff, Boff, Dd, Wv1, bv1, hid2);
    // my 4th launch = NEW g4 -> ncu captures it (same slot as the 59.8us measurement)
    {
        dim3 g(CHUNK / 64, BATCH / 64);
        gemm_kernel<false><<<g, 256>>>(hid2, Wv2, bv2, out, BATCH, CHUNK, HID, HID, CHUNK);
    }
}